// round 15
// baseline (speedup 1.0000x reference)
#include <cuda_runtime.h>

#define BATCH 512
#define TLEN 16385
#define NN 16384
#define THREADS 256
#define NGRP 4096                          // 4-elem groups per row
#define GPT 16                             // groups per thread
#define NWARP 8
#define PADG(f) ((f) + ((f) >> 4))         // pad 1 per 16 floats
#define SM_CHK (NGRP + NGRP / 16 + 4)      // 4356 floats = 17.4KB

__device__ __forceinline__ float fsqrt_a(float v) {
    float r; asm("sqrt.approx.f32 %0, %1;" : "=f"(r) : "f"(v)); return r;
}
__device__ __forceinline__ float fex2_a(float v) {
    float r; asm("ex2.approx.f32 %0, %1;" : "=f"(r) : "f"(v)); return r;
}
__device__ __forceinline__ float flg2_a(float v) {
    float r; asm("lg2.approx.f32 %0, %1;" : "=f"(r) : "f"(v)); return r;
}

__device__ __forceinline__ float warp_iscan(float v, unsigned lane) {
    #pragma unroll
    for (int d = 1; d < 32; d <<= 1) {
        float n = __shfl_up_sync(0xffffffffu, v, d);
        if (lane >= d) v += n;
    }
    return v;
}

// 5-elem window x[4f..4f+4] from two aligned float4 loads; row phase P = b&3
// (x[j] sits at global index b*16385+j === b+j mod 4; vec = xr - P is aligned).
// Bounds: underrun only for b>0 (lands in prior row, slots unused); overrun:
// row 511 has P=3 -> W1 ends exactly at x[16384]; other rows spill into the
// next row's storage (in-allocation, unused slots).
template <int P>
__device__ __forceinline__ void load_win(const float4* __restrict__ vec, int f,
                                         float& x0, float (&e)[4]) {
    float4 W0 = __ldg(vec + f);
    float4 W1 = __ldg(vec + f + 1);
    if (P == 0)      { x0 = W0.x; e[0] = W0.y; e[1] = W0.z; e[2] = W0.w; e[3] = W1.x; }
    else if (P == 1) { x0 = W0.y; e[0] = W0.z; e[1] = W0.w; e[2] = W1.x; e[3] = W1.y; }
    else if (P == 2) { x0 = W0.z; e[0] = W0.w; e[1] = W1.x; e[2] = W1.y; e[3] = W1.z; }
    else             { x0 = W0.w; e[0] = W1.x; e[1] = W1.y; e[2] = W1.z; e[3] = W1.w; }
}

// Phase 1: per-group trapezoid integrals into smem + sE accumulation.
template <int P>
__device__ __forceinline__ void phase1(const float* __restrict__ xr, float* gI,
                                       int tid, float& sE) {
    const float4* __restrict__ vec = (const float4*)(xr - P);
    #pragma unroll
    for (int g = 0; g < GPT; g++) {
        const int f = g * THREADS + tid;
        float x0, e[4];
        load_win<P>(vec, f, x0, e);
        gI[PADG(f)] = 0.5f * (x0 + e[3]) + ((e[0] + e[1]) + e[2]);
        sE = fmaf(e[0], e[0], sE); sE = fmaf(e[1], e[1], sE);
        sE = fmaf(e[2], e[2], sE); sE = fmaf(e[3], e[3], sE);
    }
}

// Phase 3: rebuild u from checkpoints, accumulate Gram/data sums.
template <int P>
__device__ __forceinline__ void phase3(const float* __restrict__ xr,
                                       const float* gI, int tid,
                                       float r, bool rhalf,
                                       float& sA, float& sB, float& sC,
                                       float& sD0, float& sD1) {
    const float4* __restrict__ vec = (const float4*)(xr - P);
    #pragma unroll
    for (int g = 0; g < GPT; g++) {
        const int f = g * THREADS + tid;
        float x0, e[4];
        load_win<P>(vec, f, x0, e);
        const float cb = gI[PADG(f)] + 0.5f * x0;
        float lps = 0.f;
        #pragma unroll
        for (int m = 0; m < 4; m++) {
            float xc = e[m];
            lps += xc;
            float u  = fmaf(-0.5f, xc, cb + lps);
            float su = rhalf ? fsqrt_a(u) : fex2_a(r * flg2_a(u));
            sA  = fmaf(u, u, sA);
            sB  = fmaf(u, su, sB);
            sC += u;
            sD0 = fmaf(xc, u, sD0);
            sD1 = fmaf(xc, su, sD1);
        }
    }
}

// Phase 5: outputs.
template <int P>
__device__ __forceinline__ void phase5(const float* __restrict__ xr,
                                       const float* gI, int tid,
                                       float c0, float c1, float r, bool rhalf,
                                       float4* __restrict__ xh4,
                                       float4* __restrict__ rs4) {
    const float4* __restrict__ vec = (const float4*)(xr - P);
    #pragma unroll
    for (int g = 0; g < GPT; g++) {
        const int f = g * THREADS + tid;
        float x0, e[4];
        load_win<P>(vec, f, x0, e);
        const float cb = gI[PADG(f)] + 0.5f * x0;
        float hv[4], rv[4];
        float lps = 0.f;
        #pragma unroll
        for (int m = 0; m < 4; m++) {
            float xc = e[m];
            lps += xc;
            float u  = fmaf(-0.5f, xc, cb + lps);
            float su = rhalf ? fsqrt_a(u) : fex2_a(r * flg2_a(u));
            float xh = fmaf(c0, u, c1 * su);
            hv[m] = xh; rv[m] = xc - xh;
        }
        xh4[f] = make_float4(hv[0], hv[1], hv[2], hv[3]);
        rs4[f] = make_float4(rv[0], rv[1], rv[2], rv[3]);
    }
}

__global__ __launch_bounds__(THREADS, 4)
void vp_kernel(const float* __restrict__ x, const float* __restrict__ params,
               float* __restrict__ o_coeffs, float* __restrict__ o_xhat,
               float* __restrict__ o_res, float* __restrict__ o_r2)
{
    __shared__ __align__(16) float gI[SM_CHK];   // group integrals -> checkpoints
    __shared__ float warp_tot[NWARP];
    __shared__ float warp_scan[NWARP];
    __shared__ float red[NWARP * 6];
    __shared__ float cbc[2];

    const int tid  = threadIdx.x;
    const int lane = tid & 31;
    const int wid  = tid >> 5;
    const int b    = blockIdx.x;
    const float* __restrict__ xr = x + (size_t)b * TLEN;
    const float r  = params[0];
    const float ny = params[1];
    const bool rhalf = (r == 0.5f);
    const int P = b & 3;

    // ---- Phase 1: group integrals (single gmem-latency exposure) ----
    float sE = 0.f;
    switch (P) {
        case 0:  phase1<0>(xr, gI, tid, sE); break;
        case 1:  phase1<1>(xr, gI, tid, sE); break;
        case 2:  phase1<2>(xr, gI, tid, sE); break;
        default: phase1<3>(xr, gI, tid, sE); break;
    }
    __syncthreads();

    // ---- Phase 2: block scan of 4096 group integrals (in place) ----
    // Thread t owns contiguous groups [16t, 16t+16); padded scalar LDS/STS
    // (stride 17 per thread) are conflict-free.
    {
        float pre[GPT];
        float runv = 0.f;
        const int gb = PADG(GPT * tid);      // = 17*tid
        #pragma unroll
        for (int i = 0; i < GPT; i++) {
            float v = gI[gb + i];
            pre[i] = runv;
            runv += v;
        }
        float incw = warp_iscan(runv, lane);
        if (lane == 31) warp_tot[wid] = incw;
        __syncthreads();
        if (wid == 0) {
            // all 32 lanes run the full-mask shfl scan (lanes >= NWARP add 0)
            float v = (lane < NWARP) ? warp_tot[lane] : 0.f;
            v = warp_iscan(v, lane);
            if (lane < NWARP) warp_scan[lane] = v;
        }
        __syncthreads();
        const float tbase = ny + (incw - runv) + (wid ? warp_scan[wid - 1] : 0.f);
        #pragma unroll
        for (int i = 0; i < GPT; i++) gI[gb + i] = tbase + pre[i];
    }
    __syncthreads();

    // ---- Phase 3: Gram/data sums ----
    float sA = 0.f, sB = 0.f, sC = 0.f, sD0 = 0.f, sD1 = 0.f;
    switch (P) {
        case 0:  phase3<0>(xr, gI, tid, r, rhalf, sA, sB, sC, sD0, sD1); break;
        case 1:  phase3<1>(xr, gI, tid, r, rhalf, sA, sB, sC, sD0, sD1); break;
        case 2:  phase3<2>(xr, gI, tid, r, rhalf, sA, sB, sC, sD0, sD1); break;
        default: phase3<3>(xr, gI, tid, r, rhalf, sA, sB, sC, sD0, sD1); break;
    }

    // ---- Block reduce + rank-1 pinv solve ----
    #pragma unroll
    for (int d = 16; d; d >>= 1) {
        sA  += __shfl_xor_sync(~0u, sA,  d);
        sB  += __shfl_xor_sync(~0u, sB,  d);
        sC  += __shfl_xor_sync(~0u, sC,  d);
        sD0 += __shfl_xor_sync(~0u, sD0, d);
        sD1 += __shfl_xor_sync(~0u, sD1, d);
        sE  += __shfl_xor_sync(~0u, sE,  d);
    }
    if (lane == 0) {
        red[wid * 6 + 0] = sA;  red[wid * 6 + 1] = sB;
        red[wid * 6 + 2] = sC;  red[wid * 6 + 3] = sD0;
        red[wid * 6 + 4] = sD1; red[wid * 6 + 5] = sE;
    }
    __syncthreads();
    if (tid == 0) {
        double A = 0, Bb = 0, C = 0, D0 = 0, D1 = 0, E = 0;
        for (int w = 0; w < NWARP; w++) {
            A  += red[w * 6 + 0]; Bb += red[w * 6 + 1];
            C  += red[w * 6 + 2]; D0 += red[w * 6 + 3];
            D1 += red[w * 6 + 4]; E  += red[w * 6 + 5];
        }
        // JAX pinv rcond = 10*max(M,N)*eps truncates sigma_2 -> rank-1 solve
        double hh  = 0.5 * (A - C);
        double s   = sqrt(hh * hh + Bb * Bb);
        double lam = 0.5 * (A + C) + s;          // lambda_1 of Gram
        double w0  = Bb;
        double w1  = Bb * Bb / (hh + s);         // = lam - A, stable form
        double n2  = w0 * w0 + w1 * w1;
        double beta = (w0 * D0 + w1 * D1) / (lam * n2);
        double c0d = beta * w0, c1d = beta * w1;
        float c0 = (float)c0d, c1 = (float)c1d;
        cbc[0] = c0; cbc[1] = c1;
        o_coeffs[b * 2 + 0] = c0;
        o_coeffs[b * 2 + 1] = c1;
        // analytic r2 = E - 2 c.d + c^T G c  (G = [[A,Bb],[Bb,C]])
        double r2 = E - 2.0 * (c0d * D0 + c1d * D1)
                  + (c0d * c0d * A + 2.0 * c0d * c1d * Bb + c1d * c1d * C);
        o_r2[b] = (float)r2;
    }
    __syncthreads();
    const float c0 = cbc[0];
    const float c1 = cbc[1];

    // ---- Phase 5: outputs ----
    float4* __restrict__ xh4 = (float4*)(o_xhat + (size_t)b * NN);
    float4* __restrict__ rs4 = (float4*)(o_res  + (size_t)b * NN);
    switch (P) {
        case 0:  phase5<0>(xr, gI, tid, c0, c1, r, rhalf, xh4, rs4); break;
        case 1:  phase5<1>(xr, gI, tid, c0, c1, r, rhalf, xh4, rs4); break;
        case 2:  phase5<2>(xr, gI, tid, c0, c1, r, rhalf, xh4, rs4); break;
        default: phase5<3>(xr, gI, tid, c0, c1, r, rhalf, xh4, rs4); break;
    }
}

extern "C" void kernel_launch(void* const* d_in, const int* in_sizes, int n_in,
                              void* d_out, int out_size)
{
    const float* x      = (const float*)d_in[0];
    const float* params = (const float*)d_in[1];
    if (n_in >= 2 && in_sizes[0] == 2) {       // defensive: metadata order swap
        x      = (const float*)d_in[1];
        params = (const float*)d_in[0];
    }
    float* out      = (float*)d_out;
    float* o_coeffs = out;                                   // 512*1*2
    float* o_xhat   = out + (size_t)BATCH * 2;               // 512*1*16384
    float* o_res    = o_xhat + (size_t)BATCH * NN;           // 512*1*16384
    float* o_r2     = o_res  + (size_t)BATCH * NN;           // 512*1

    vp_kernel<<<BATCH, THREADS>>>(x, params, o_coeffs, o_xhat, o_res, o_r2);
}

// round 16
// speedup vs baseline: 1.4671x; 1.4671x over previous
#include <cuda_runtime.h>

#define BATCH 512
#define TLEN 16385
#define NN 16384
#define THREADS 256
#define HALF 8192
#define NWARP 8
#define PADL(j) ((j) + (((j) >> 5) << 2))      // pad 4 per 32 -> float4-friendly
#define XS_WORDS 9220                          // PADL(8192)+1=9217, pad to 16B
#define CHK 4096                               // one checkpoint per 4-elem group
#define SMEM_TOT (XS_WORDS + CHK)              // 13316 floats = 53.3KB

__device__ __forceinline__ float fsqrt_a(float v) {
    float r; asm("sqrt.approx.f32 %0, %1;" : "=f"(r) : "f"(v)); return r;
}
__device__ __forceinline__ float fex2_a(float v) {
    float r; asm("ex2.approx.f32 %0, %1;" : "=f"(r) : "f"(v)); return r;
}
__device__ __forceinline__ float flg2_a(float v) {
    float r; asm("lg2.approx.f32 %0, %1;" : "=f"(r) : "f"(v)); return r;
}

__device__ __forceinline__ float warp_iscan(float v, unsigned lane) {
    #pragma unroll
    for (int d = 1; d < 32; d <<= 1) {
        float n = __shfl_up_sync(0xffffffffu, v, d);
        if (lane >= d) v += n;
    }
    return v;
}

// Vectorized stage: row-phase P = (global index of xh[0]) & 3 is CTA-constant.
template <int P>
__device__ __forceinline__ void stage_vec(float* xs, const float* __restrict__ xh,
                                          int tid) {
    const float4* __restrict__ vec = (const float4*)(xh - P);
    #pragma unroll
    for (int k = 0; k < 8; k++) {
        const int q = k * THREADS + tid;            // group in [0,2048)
        float4 V0 = __ldg(vec + q);
        float e0, e1, e2, e3;
        if (P == 0) { e0 = V0.x; e1 = V0.y; e2 = V0.z; e3 = V0.w; }
        else {
            float4 V1 = __ldg(vec + q + 1);         // overlaps lane+1's V0
            if (P == 1) { e0 = V0.y; e1 = V0.z; e2 = V0.w; e3 = V1.x; }
            if (P == 2) { e0 = V0.z; e1 = V0.w; e2 = V1.x; e3 = V1.y; }
            if (P == 3) { e0 = V0.w; e1 = V1.x; e2 = V1.y; e3 = V1.z; }
        }
        *(float4*)(xs + PADL(4 * q)) = make_float4(e0, e1, e2, e3);
    }
    if (tid == 0) xs[PADL(HALF)] = xh[HALF];
}

__device__ __forceinline__ void stage_dispatch(float* xs, const float* xh,
                                               int tid, int P) {
    switch (P) {
        case 0:  stage_vec<0>(xs, xh, tid); break;
        case 1:  stage_vec<1>(xs, xh, tid); break;
        case 2:  stage_vec<2>(xs, xh, tid); break;
        default: stage_vec<3>(xs, xh, tid); break;
    }
}

// Direct-gmem output for half 0: xd window x[4f+1..4f+4], phase S=(b+1)&3.
template <int S>
__device__ __forceinline__ void out_h0(const float* __restrict__ xr,
                                       const float* __restrict__ chk,
                                       float c0, float c1, float r, bool rhalf,
                                       float4* __restrict__ xh4,
                                       float4* __restrict__ rs4, int tid)
{
    const float4* __restrict__ xv = (const float4*)(xr + 1 - S);
    #pragma unroll
    for (int g = 0; g < 8; g++) {
        const int f = g * THREADS + tid;            // chunk in [0,2048), half 0
        float4 V0 = __ldg(xv + f);
        float e[4];
        if (S == 0) { e[0] = V0.x; e[1] = V0.y; e[2] = V0.z; e[3] = V0.w; }
        else {
            float4 V1 = __ldg(xv + f + 1);
            if (S == 1) { e[0] = V0.y; e[1] = V0.z; e[2] = V0.w; e[3] = V1.x; }
            if (S == 2) { e[0] = V0.z; e[1] = V0.w; e[2] = V1.x; e[3] = V1.y; }
            if (S == 3) { e[0] = V0.w; e[1] = V1.x; e[2] = V1.y; e[3] = V1.z; }
        }
        const float cb = chk[f];
        float hv[4], rv[4];
        float pl = 0.f;
        #pragma unroll
        for (int m = 0; m < 4; m++) {
            float xc = e[m];
            pl += xc;
            float u  = fmaf(-0.5f, xc, cb + pl);
            float su = rhalf ? fsqrt_a(u) : fex2_a(r * flg2_a(u));
            float xh = fmaf(c0, u, c1 * su);
            hv[m] = xh; rv[m] = xc - xh;
        }
        xh4[f] = make_float4(hv[0], hv[1], hv[2], hv[3]);
        rs4[f] = make_float4(rv[0], rv[1], rv[2], rv[3]);
    }
}

__global__ __launch_bounds__(THREADS, 4)
void vp_kernel(const float* __restrict__ x, const float* __restrict__ params,
               float* __restrict__ o_coeffs, float* __restrict__ o_xhat,
               float* __restrict__ o_res, float* __restrict__ o_r2)
{
    extern __shared__ __align__(16) float smem[];
    float* xs  = smem;                        // staged half row (padded)
    float* chk = smem + XS_WORDS;             // group-base checkpoints, full row
    __shared__ float warp_tot[NWARP];
    __shared__ float red[NWARP * 6];

    const int tid  = threadIdx.x;
    const int lane = tid & 31;
    const int wid  = tid >> 5;
    const int b    = blockIdx.x;
    const float* __restrict__ xr = x + (size_t)b * TLEN;
    const float r  = params[0];
    const float ny = params[1];
    const bool rhalf = (r == 0.5f);
    const int P = b & 3;                      // stage phase (16385 % 4 == 1)

    // blocked view for reduction: thread owns x[32t..32t+32]
    const float4* __restrict__ xt4 = (const float4*)(xs + 36 * tid);
    const int blast = 36 * tid + 36;

    float uoff = ny;
    float sA = 0.f, sB = 0.f, sC = 0.f, sD0 = 0.f, sD1 = 0.f, sE = 0.f;

    // ================= Reduction passes over both halves =================
    #pragma unroll 1
    for (int h = 0; h < 2; h++) {
        stage_dispatch(xs, xr + h * HALF, tid, P);
        __syncthreads();

        // per-thread trapezoid total (4 chains): tot = T + 0.5*(xlast - f0)
        float f0, tot;
        {
            float4 v0 = xt4[0];
            f0 = v0.x;
            float t0 = v0.x, t1 = v0.y, t2 = v0.z, t3 = v0.w;
            #pragma unroll
            for (int g = 1; g < 8; g++) {
                float4 v = xt4[g];
                t0 += v.x; t1 += v.y; t2 += v.z; t3 += v.w;
            }
            tot = ((t0 + t1) + (t2 + t3)) + 0.5f * (xs[blast] - f0);
        }
        float incw = warp_iscan(tot, lane);
        if (lane == 31) warp_tot[wid] = incw;
        __syncthreads();

        // Redundant cross-warp prefix: every thread scans the 8 warp totals
        // itself (broadcast LDS) -- no wid==0 block, no second barrier.
        float wpre = 0.f, wall = 0.f;
        #pragma unroll
        for (int w = 0; w < NWARP; w++) {
            float v = warp_tot[w];
            if (w < wid) wpre += v;
            wall += v;
        }
        const float bs = uoff + (incw - tot) + wpre;
        const float b2 = bs + 0.5f * f0;     // u_k = b2 + ps_k - 0.5*xc_k

        // streaming sums + checkpoint per 4-elem group (global group id)
        float ps = 0.f;
        float4 cur = xt4[0];
        #pragma unroll
        for (int g = 0; g < 8; g++) {
            chk[h * 2048 + 8 * tid + g] = b2 + ps;
            float4 nxt;
            if (g < 7) nxt = xt4[g + 1];
            else { nxt.x = xs[blast]; nxt.y = nxt.z = nxt.w = 0.f; }
            float e[4] = {cur.y, cur.z, cur.w, nxt.x};
            #pragma unroll
            for (int m = 0; m < 4; m++) {
                float xc = e[m];
                ps += xc;
                float u  = fmaf(-0.5f, xc, b2 + ps);
                float su = rhalf ? fsqrt_a(u) : fex2_a(r * flg2_a(u));
                sA  = fmaf(u, u, sA);
                sB  = fmaf(u, su, sB);
                sC += u;
                sD0 = fmaf(xc, u, sD0);
                sD1 = fmaf(xc, su, sD1);
                sE  = fmaf(xc, xc, sE);
            }
            cur = nxt;
        }
        uoff += wall;                        // half total (consistent all threads)
        __syncthreads();                     // xs/warp_tot reads done before reuse
    }

    // ================= Block reduce + redundant fp32 rank-1 solve ==========
    #pragma unroll
    for (int d = 16; d; d >>= 1) {
        sA  += __shfl_xor_sync(~0u, sA,  d);
        sB  += __shfl_xor_sync(~0u, sB,  d);
        sC  += __shfl_xor_sync(~0u, sC,  d);
        sD0 += __shfl_xor_sync(~0u, sD0, d);
        sD1 += __shfl_xor_sync(~0u, sD1, d);
        sE  += __shfl_xor_sync(~0u, sE,  d);
    }
    if (lane == 0) {
        red[wid * 6 + 0] = sA;  red[wid * 6 + 1] = sB;
        red[wid * 6 + 2] = sC;  red[wid * 6 + 3] = sD0;
        red[wid * 6 + 4] = sD1; red[wid * 6 + 5] = sE;
    }
    __syncthreads();

    // Every thread reduces red[] (broadcast LDS) and solves; no serial tail.
    // JAX pinv rcond = 10*max(M,N)*eps truncates sigma_2 -> rank-1 solve.
    float c0, c1;
    {
        float A = 0.f, Bb = 0.f, C = 0.f, D0 = 0.f, D1 = 0.f, E = 0.f;
        #pragma unroll
        for (int w = 0; w < NWARP; w++) {
            A  += red[w * 6 + 0]; Bb += red[w * 6 + 1];
            C  += red[w * 6 + 2]; D0 += red[w * 6 + 3];
            D1 += red[w * 6 + 4]; E  += red[w * 6 + 5];
        }
        float hh  = 0.5f * (A - C);
        float s   = sqrtf(fmaf(hh, hh, Bb * Bb));
        float lam = 0.5f * (A + C) + s;          // lambda_1 of Gram
        float w0  = Bb;
        float w1  = Bb * Bb / (hh + s);          // = lam - A, stable form
        float n2  = fmaf(w0, w0, w1 * w1);
        float beta = fmaf(w0, D0, w1 * D1) / (lam * n2);
        c0 = beta * w0;
        c1 = beta * w1;
        if (tid == 0) {
            o_coeffs[b * 2 + 0] = c0;
            o_coeffs[b * 2 + 1] = c1;
            // analytic r2 = E - 2 c.d + c^T G c  (G = [[A,Bb],[Bb,C]])
            float r2 = E - 2.f * fmaf(c0, D0, c1 * D1)
                     + (c0 * c0 * A + 2.f * c0 * c1 * Bb + c1 * c1 * C);
            o_r2[b] = r2;
        }
    }

    // ================= Outputs =================
    float4* __restrict__ xh4 = (float4*)(o_xhat + (size_t)b * NN);
    float4* __restrict__ rs4 = (float4*)(o_res  + (size_t)b * NN);

    // --- half 0: direct gmem (no restage) ---
    switch ((b + 1) & 3) {
        case 0:  out_h0<0>(xr, chk, c0, c1, r, rhalf, xh4, rs4, tid); break;
        case 1:  out_h0<1>(xr, chk, c0, c1, r, rhalf, xh4, rs4, tid); break;
        case 2:  out_h0<2>(xr, chk, c0, c1, r, rhalf, xh4, rs4, tid); break;
        default: out_h0<3>(xr, chk, c0, c1, r, rhalf, xh4, rs4, tid); break;
    }

    // --- half 1: from resident smem (still holds half 1) ---
    {
        const float4* __restrict__ xs4 = (const float4*)xs;
        #pragma unroll
        for (int g = 0; g < 8; g++) {
            const int f = g * THREADS + tid;           // local chunk in half 1
            float4 v = xs4[f + (f >> 3)];              // padded float4 view
            float nx = __shfl_down_sync(0xffffffffu, v.x, 1);
            if (lane == 31) nx = xs[PADL(4 * f + 4)];  // warp-edge boundary
            const float cb = chk[2048 + f];
            float e[4] = {v.y, v.z, v.w, nx};
            float hv[4], rv[4];
            float pl = 0.f;
            #pragma unroll
            for (int m = 0; m < 4; m++) {
                float xc = e[m];
                pl += xc;
                float u  = fmaf(-0.5f, xc, cb + pl);
                float su = rhalf ? fsqrt_a(u) : fex2_a(r * flg2_a(u));
                float xv = fmaf(c0, u, c1 * su);
                hv[m] = xv; rv[m] = xc - xv;
            }
            const int o4 = 2048 + f;
            xh4[o4] = make_float4(hv[0], hv[1], hv[2], hv[3]);
            rs4[o4] = make_float4(rv[0], rv[1], rv[2], rv[3]);
        }
    }
}

extern "C" void kernel_launch(void* const* d_in, const int* in_sizes, int n_in,
                              void* d_out, int out_size)
{
    const float* x      = (const float*)d_in[0];
    const float* params = (const float*)d_in[1];
    if (n_in >= 2 && in_sizes[0] == 2) {       // defensive: metadata order swap
        x      = (const float*)d_in[1];
        params = (const float*)d_in[0];
    }
    float* out      = (float*)d_out;
    float* o_coeffs = out;                                   // 512*1*2
    float* o_xhat   = out + (size_t)BATCH * 2;               // 512*1*16384
    float* o_res    = o_xhat + (size_t)BATCH * NN;           // 512*1*16384
    float* o_r2     = o_res  + (size_t)BATCH * NN;           // 512*1

    size_t smem = SMEM_TOT * sizeof(float);
    cudaFuncSetAttribute(vp_kernel, cudaFuncAttributeMaxDynamicSharedMemorySize,
                         (int)smem);
    vp_kernel<<<BATCH, THREADS, smem>>>(x, params, o_coeffs, o_xhat, o_res, o_r2);
}